// round 14
// baseline (speedup 1.0000x reference)
#include <cuda_runtime.h>
#include <math.h>
#include <stdint.h>

#define TPB 256
#define SEQL 3072
#define DMODEL 1024
#define NHEAD 16
#define DHEAD 64
#define SPRIME 768      // SEQL / 4 (dilation)
#define KTILE 192       // 127 + 64 key rows per attention tile
#define QTILE 64
#define KBLKS (DMODEL / 8)   // 128

// ---------------- scratch (device globals; no allocation allowed) -------------
__device__ __align__(16) float g_q[NHEAD * 4 * SPRIME * DHEAD];
__device__ __align__(16) float g_k[NHEAD * 4 * SPRIME * DHEAD];
__device__ __align__(16) float g_v[NHEAD * 4 * SPRIME * DHEAD];
__device__ __align__(16) float g_ctx[SEQL * DMODEL];
// fragment-packed operands (tf32-rounded):
__device__ __align__(16) float g_packX[SEQL * DMODEL];       // A-frag pack of x
__device__ __align__(16) float g_packC[SEQL * DMODEL];       // A-frag pack of ctx
__device__ __align__(16) float g_packW[4 * DMODEL * DMODEL]; // B-frag packs Wq,Wk,Wv,Wo

// ---------------- tf32 helpers -----------------------------------------------
__device__ __forceinline__ unsigned f2tf(float f) {
    unsigned u;
    asm("cvt.rna.tf32.f32 %0, %1;" : "=r"(u) : "f"(f));
    return u;
}

__device__ __forceinline__ void mma8(float* c, const unsigned* a, const unsigned* b) {
    asm volatile(
        "mma.sync.aligned.m16n8k8.row.col.f32.tf32.tf32.f32 "
        "{%0,%1,%2,%3}, {%4,%5,%6,%7}, {%8,%9}, {%0,%1,%2,%3};"
        : "+f"(c[0]), "+f"(c[1]), "+f"(c[2]), "+f"(c[3])
        : "r"(a[0]), "r"(a[1]), "r"(a[2]), "r"(a[3]),
          "r"(b[0]), "r"(b[1]));
}

// ---------------- cp.async helpers --------------------------------------------
__device__ __forceinline__ void cpasync16(void* s, const void* g) {
    unsigned saddr = (unsigned)__cvta_generic_to_shared(s);
    asm volatile("cp.async.cg.shared.global [%0], [%1], 16;\n" :: "r"(saddr), "l"(g));
}
__device__ __forceinline__ void cpcommit() {
    asm volatile("cp.async.commit_group;\n");
}
template<int N> __device__ __forceinline__ void cpwait() {
    asm volatile("cp.async.wait_group %0;\n" :: "n"(N));
}

// ---------------- pack kernels -------------------------------------------------
__global__ void __launch_bounds__(256) pack_a_kernel(const float* __restrict__ xsrc,
                                                     int mode) {
    const float* src = (mode == 0) ? xsrc : g_ctx;
    float* dst       = (mode == 0) ? g_packX : g_packC;
    const unsigned u = blockIdx.x * 256 + threadIdx.x;   // one float4 out
    const unsigned l = u & 31, blk = u >> 5;
    const unsigned KB = blk & (KBLKS - 1), MB = blk >> 7;
    const unsigned gid = l >> 2, tig = l & 3;
    const float* p = src + (size_t)(MB * 16 + gid) * DMODEL + KB * 8 + tig;
    uint4 o;
    o.x = f2tf(p[0]);
    o.y = f2tf(p[8 * DMODEL]);
    o.z = f2tf(p[4]);
    o.w = f2tf(p[8 * DMODEL + 4]);
    *((uint4*)dst + u) = o;
}

__global__ void __launch_bounds__(256) pack_b_kernel(
    const float* __restrict__ Wq, const float* __restrict__ Wk,
    const float* __restrict__ Wv, const float* __restrict__ Wo) {
    const int z = blockIdx.y;
    const float* W = (z == 0) ? Wq : ((z == 1) ? Wk : ((z == 2) ? Wv : Wo));
    float* dst = g_packW + (size_t)z * DMODEL * DMODEL;
    const unsigned u = blockIdx.x * 256 + threadIdx.x;   // one float2 out
    const unsigned l = u & 31, blk = u >> 5;
    const unsigned KB = blk & (KBLKS - 1), NB = blk >> 7;
    const unsigned gid = l >> 2, tig = l & 3;
    const float* p = W + (size_t)(NB * 8 + gid) * DMODEL + KB * 8 + tig;
    uint2 o;
    o.x = f2tf(p[0]);
    o.y = f2tf(p[4]);
    *((uint2*)dst + u) = o;
}

// ---------------- packed-fragment GEMM: C[128x128] -----------------------------
#define GBK 32
#define GNCH (DMODEL / GBK)                  // 32
#define CHUNK_F 4096                         // floats per operand chunk (16KB)
#define GEMM_SMEM_BYTES (4 * CHUNK_F * 4)    // 65536

__device__ __forceinline__ void gemm_body(const float* __restrict__ Ap,
                                          const float* __restrict__ Bp,
                                          int mb0, int nb0,
                                          float (&c)[2][8][4], float* sm) {
    float* sA[2] = { sm, sm + CHUNK_F };
    float* sB[2] = { sm + 2 * CHUNK_F, sm + 3 * CHUNK_F };

    const int tid  = threadIdx.x;
    const int lane = tid & 31, warp = tid >> 5;
    const int wm2 = (warp & 3) * 2;     // chunk-local mblk base
    const int wn8 = (warp >> 2) * 8;    // chunk-local nblk base

    auto stage = [&](int ch, int b) {
        const int kb0 = ch * 4;
        #pragma unroll
        for (int t = 0; t < 4; t++) {
            unsigned u = tid + t * 256;            // A 16B-unit
            unsigned i = u >> 7, j = (u >> 5) & 3, l = u & 31;
            const float* srcA = Ap + ((size_t)((mb0 + i) * KBLKS + kb0 + j) * 32 + l) * 4;
            cpasync16(sA[b] + u * 4, srcA);
        }
        #pragma unroll
        for (int t = 0; t < 4; t++) {
            unsigned u = tid + t * 256;            // B 16B-unit (2 lanes x float2)
            unsigned inb = u >> 6, rem = u & 63;
            unsigned j = rem >> 4, lp = (rem & 15) * 2;
            const float* srcB = Bp + ((size_t)((nb0 + inb) * KBLKS + kb0 + j) * 32 + lp) * 2;
            cpasync16(sB[b] + u * 4, srcB);
        }
        cpcommit();
    };

    stage(0, 0);

    for (int ch = 0; ch < GNCH; ch++) {
        const int b = ch & 1;
        if (ch + 1 < GNCH) { stage(ch + 1, b ^ 1); cpwait<1>(); }
        else               { cpwait<0>(); }
        __syncthreads();

        const float* a_s = sA[b];
        const float* b_s = sB[b];
        #pragma unroll
        for (int ks8 = 0; ks8 < 4; ks8++) {
            uint4 a[2];
            uint2 bb[8];
            #pragma unroll
            for (int mt = 0; mt < 2; mt++)
                a[mt] = *(const uint4*)(a_s + (((wm2 + mt) * 4 + ks8) * 32 + lane) * 4);
            #pragma unroll
            for (int nt = 0; nt < 8; nt++)
                bb[nt] = *(const uint2*)(b_s + (((wn8 + nt) * 4 + ks8) * 32 + lane) * 2);
            #pragma unroll
            for (int mt = 0; mt < 2; mt++)
                #pragma unroll
                for (int nt = 0; nt < 8; nt++)
                    mma8(c[mt][nt], (const unsigned*)&a[mt], (const unsigned*)&bb[nt]);
        }
        __syncthreads();
    }
}

// ---------------- QKV projection -----------------------------------------------
__global__ void __launch_bounds__(TPB, 2) qkv_kernel(
    const float* __restrict__ bq, const float* __restrict__ bk,
    const float* __restrict__ bv, const float* __restrict__ beta)
{
    extern __shared__ float sm[];
    const int z = blockIdx.z;
    const float* Bp   = g_packW + (size_t)z * DMODEL * DMODEL;
    const float* bias = (z == 0) ? bq : ((z == 1) ? bk : bv);
    float* outp       = (z == 0) ? g_q : ((z == 1) ? g_k : g_v);
    const int m0 = blockIdx.y * 128, n0 = blockIdx.x * 128;

    float c[2][8][4];
    #pragma unroll
    for (int mt = 0; mt < 2; mt++)
        #pragma unroll
        for (int nt = 0; nt < 8; nt++)
            #pragma unroll
            for (int k = 0; k < 4; k++) c[mt][nt][k] = 0.f;

    gemm_body(g_packX, Bp, m0 / 16, n0 / 8, c, sm);

    const int lane = threadIdx.x & 31, warp = threadIdx.x >> 5;
    const int wm = (warp & 3) * 32, wn = (warp >> 2) * 64;
    const int gid = lane >> 2, tig = lane & 3;

    #pragma unroll
    for (int mt = 0; mt < 2; mt++) {
        #pragma unroll
        for (int nt = 0; nt < 8; nt++) {
            int n_c = n0 + wn + nt * 8 + tig * 2;
            int h = n_c >> 6, d0 = n_c & 63;
            float sc = 1.0f;
            if (z == 0) sc = 0.125f * __expf(-beta[h]);   // fold 1/(8*exp(beta)) into Q
            float b0 = bias[n_c], b1 = bias[n_c + 1];
            #pragma unroll
            for (int half = 0; half < 2; half++) {
                int s  = m0 + wm + mt * 16 + gid + half * 8;
                int rr = s & 3, sp = s >> 2;
                float v0 = (c[mt][nt][half * 2 + 0] + b0) * sc;
                float v1 = (c[mt][nt][half * 2 + 1] + b1) * sc;
                float2* dst = (float2*)(outp + (((h * 4 + rr) * SPRIME + sp) * DHEAD + d0));
                *dst = make_float2(v0, v1);
            }
        }
    }
}

// ---------------- output projection --------------------------------------------
__global__ void __launch_bounds__(TPB, 2) oproj_kernel(
    const float* __restrict__ bo, float* __restrict__ out)
{
    extern __shared__ float sm[];
    const int m0 = blockIdx.y * 128, n0 = blockIdx.x * 128;

    float c[2][8][4];
    #pragma unroll
    for (int mt = 0; mt < 2; mt++)
        #pragma unroll
        for (int nt = 0; nt < 8; nt++)
            #pragma unroll
            for (int k = 0; k < 4; k++) c[mt][nt][k] = 0.f;

    gemm_body(g_packC, g_packW + (size_t)3 * DMODEL * DMODEL, m0 / 16, n0 / 8, c, sm);

    const int lane = threadIdx.x & 31, warp = threadIdx.x >> 5;
    const int wm = (warp & 3) * 32, wn = (warp >> 2) * 64;
    const int gid = lane >> 2, tig = lane & 3;

    #pragma unroll
    for (int mt = 0; mt < 2; mt++) {
        #pragma unroll
        for (int nt = 0; nt < 8; nt++) {
            int n_c = n0 + wn + nt * 8 + tig * 2;
            float b0 = bo[n_c], b1 = bo[n_c + 1];
            #pragma unroll
            for (int half = 0; half < 2; half++) {
                int mrow = m0 + wm + mt * 16 + gid + half * 8;
                float2* dst = (float2*)(out + (size_t)mrow * DMODEL + n_c);
                *dst = make_float2(c[mt][nt][half * 2 + 0] + b0,
                                   c[mt][nt][half * 2 + 1] + b1);
            }
        }
    }
}

// ---------------- attention over dilated windows (2 CTA/SM version) ------------
// smem: sK [192][SQR=68] | sVt [64][SVR=197]; sS [64][SSR=196] ALIASES sK.
// Phase 1 warp grid: 2 row-groups (32 rows) x 4 col-quarters (48 cols).
// Band-skip: only nt tiles intersecting [R0, R0+158] are computed (balanced,
// 5 of 6 tiles per warp on average); skipped cells are out-of-band and phase 2
// zero-writes them. Q fragments are loaded from global in-loop (L1-resident).
#define SQR 68
#define SVR 197
#define SSR 196
#define ATTN_SMEM_FLOATS (KTILE * SQR + 64 * SVR)       // 13056 + 12608 = 25664
#define ATTN_SMEM_BYTES (ATTN_SMEM_FLOATS * 4)          // 102656 -> 2 CTAs/SM

__global__ void __launch_bounds__(TPB, 2) attn_kernel() {
    extern __shared__ float smA[];
    float* sK  = smA;                      // [192][SQR]
    float* sVt = smA + KTILE * SQR;        // [64][SVR]
    float* sS  = smA;                      // [64][SSR] alias of sK block

    const int tid = threadIdx.x;
    const int lane = tid & 31, warp = tid >> 5;
    const int gid = lane >> 2, tig = lane & 3;
    const int qt = blockIdx.x, r = blockIdx.y, h = blockIdx.z;
    const int q0 = qt * QTILE;
    const int kbase = q0 - 127;
    const float* Qb = g_q + (h * 4 + r) * SPRIME * DHEAD;
    const float* Kb = g_k + (h * 4 + r) * SPRIME * DHEAD;
    const float* Vb = g_v + (h * 4 + r) * SPRIME * DHEAD;

    // ---- stage K row-major + V transposed (zero-fill out-of-range j) ----
    #pragma unroll
    for (int i = 0; i < 12; i++) {
        int lin = tid + i * TPB;
        int rk = lin >> 4, dg = (lin & 15) * 4;
        int j = kbase + rk;
        float4 kv = make_float4(0.f, 0.f, 0.f, 0.f);
        float4 vv = make_float4(0.f, 0.f, 0.f, 0.f);
        if (j >= 0 && j < SPRIME) {
            kv = *(const float4*)(Kb + j * DHEAD + dg);
            vv = *(const float4*)(Vb + j * DHEAD + dg);
        }
        *(float4*)(sK + rk * SQR + dg) = kv;
        sVt[(dg + 0) * SVR + rk] = vv.x;
        sVt[(dg + 1) * SVR + rk] = vv.y;
        sVt[(dg + 2) * SVR + rk] = vv.z;
        sVt[(dg + 3) * SVR + rk] = vv.w;
    }
    __syncthreads();

    // ---- phase 1: S = Q.K^T via 3xTF32, 2m x 4n warp grid + band skip ----
    const int R0 = (warp & 1) * 32;            // row-group base (32 rows)
    const int wq = (warp >> 1) * 48;           // col-quarter base (6 nt tiles)

    float c[2][6][4];
    #pragma unroll
    for (int mt = 0; mt < 2; mt++)
        #pragma unroll
        for (int nt = 0; nt < 6; nt++)
            #pragma unroll
            for (int k = 0; k < 4; k++) c[mt][nt][k] = 0.f;

    #pragma unroll
    for (int ks8 = 0; ks8 < 8; ks8++) {
        const int ks = ks8 * 8;
        // K fragments for this warp's 6 col tiles (band-skipped)
        unsigned bh[6][2], bl[6][2];
        #pragma unroll
        for (int nt = 0; nt < 6; nt++) {
            int s = wq + nt * 8;
            if (s + 7 < R0 || s > R0 + 158) continue;
            int cb = s + gid;
            float y0 = sK[cb * SQR + ks + tig];
            float y1 = sK[cb * SQR + ks + tig + 4];
            bh[nt][0] = f2tf(y0); bl[nt][0] = f2tf(y0 - __uint_as_float(bh[nt][0]));
            bh[nt][1] = f2tf(y1); bl[nt][1] = f2tf(y1 - __uint_as_float(bh[nt][1]));
        }
        #pragma unroll
        for (int mt = 0; mt < 2; mt++) {
            // Q fragment from global (L1-resident)
            const float* qp = Qb + (q0 + R0 + mt * 16 + gid) * DHEAD + ks + tig;
            float x0 = qp[0];
            float x1 = qp[8 * DHEAD];
            float x2 = qp[4];
            float x3 = qp[8 * DHEAD + 4];
            unsigned ah[4], al[4];
            ah[0] = f2tf(x0); al[0] = f2tf(x0 - __uint_as_float(ah[0]));
            ah[1] = f2tf(x1); al[1] = f2tf(x1 - __uint_as_float(ah[1]));
            ah[2] = f2tf(x2); al[2] = f2tf(x2 - __uint_as_float(ah[2]));
            ah[3] = f2tf(x3); al[3] = f2tf(x3 - __uint_as_float(ah[3]));
            #pragma unroll
            for (int nt = 0; nt < 6; nt++) {
                int s = wq + nt * 8;
                if (s + 7 < R0 || s > R0 + 158) continue;
                mma8(c[mt][nt], ah, bh[nt]);
                mma8(c[mt][nt], ah, bl[nt]);
                mma8(c[mt][nt], al, bh[nt]);
            }
        }
    }
    __syncthreads();     // all K reads complete before S overwrites the block

    #pragma unroll
    for (int mt = 0; mt < 2; mt++) {
        #pragma unroll
        for (int nt = 0; nt < 6; nt++) {
            int s = wq + nt * 8;
            if (s + 7 < R0 || s > R0 + 158) continue;
            int col = s + tig * 2;
            int row = R0 + mt * 16 + gid;
            *(float2*)(sS + row * SSR + col) = make_float2(c[mt][nt][0], c[mt][nt][1]);
            *(float2*)(sS + (row + 8) * SSR + col) = make_float2(c[mt][nt][2], c[mt][nt][3]);
        }
    }
    __syncthreads();

    // ---- phase 2: softmax per query over its band (fast exp) ----
    {
        const int q = tid >> 2, sub = tid & 3;
        int lo = q;
        int lim = 127 - q0;
        if (lim > lo) lo = lim;
        const int hi = q + 127;
        float* row = sS + q * SSR;

        float mx = -3.0e38f;
        for (int rk = lo + sub; rk <= hi; rk += 4)
            mx = fmaxf(mx, row[rk]);
        mx = fmaxf(mx, __shfl_xor_sync(0xffffffffu, mx, 1));
        mx = fmaxf(mx, __shfl_xor_sync(0xffffffffu, mx, 2));

        float sum = 0.f;
        for (int rk = lo + sub; rk <= hi; rk += 4)
            sum += __expf(row[rk] - mx);
        sum += __shfl_xor_sync(0xffffffffu, sum, 1);
        sum += __shfl_xor_sync(0xffffffffu, sum, 2);
        const float inv = 1.0f / sum;

        for (int rk = sub; rk < KTILE; rk += 4) {
            float p = 0.f;
            if (rk >= lo && rk <= hi)
                p = __expf(row[rk] - mx) * inv;
            row[rk] = p;
        }
    }
    __syncthreads();

    // ---- phase 3: ctx = P.V via tf32 mma (unchanged mapping) ----
    {
        const int wm4 = (warp & 3) * 16;
        const int wn3 = (warp >> 2) * 32;
        const int rq  = wm4 + gid;
        float cc[4][4];
        #pragma unroll
        for (int nt = 0; nt < 4; nt++)
            #pragma unroll
            for (int k = 0; k < 4; k++) cc[nt][k] = 0.f;

        #pragma unroll 4
        for (int ks = 0; ks < KTILE; ks += 8) {
            unsigned a[4], b[4][2];
            a[0] = f2tf(sS[rq * SSR + ks + tig]);
            a[1] = f2tf(sS[(rq + 8) * SSR + ks + tig]);
            a[2] = f2tf(sS[rq * SSR + ks + tig + 4]);
            a[3] = f2tf(sS[(rq + 8) * SSR + ks + tig + 4]);
            #pragma unroll
            for (int nt = 0; nt < 4; nt++) {
                int dn = wn3 + nt * 8 + gid;
                b[nt][0] = f2tf(sVt[dn * SVR + ks + tig]);
                b[nt][1] = f2tf(sVt[dn * SVR + ks + tig + 4]);
            }
            #pragma unroll
            for (int nt = 0; nt < 4; nt++)
                mma8(cc[nt], a, b[nt]);
        }
        #pragma unroll
        for (int nt = 0; nt < 4; nt++) {
            int dn = wn3 + nt * 8 + tig * 2;
            #pragma unroll
            for (int half = 0; half < 2; half++) {
                int ql = wm4 + gid + half * 8;
                int s = (q0 + ql) * 4 + r;
                *(float2*)(g_ctx + (size_t)s * DMODEL + h * DHEAD + dn) =
                    make_float2(cc[nt][half * 2 + 0], cc[nt][half * 2 + 1]);
            }
        }
    }
}

// ---------------- launch --------------------------------------------------------
extern "C" void kernel_launch(void* const* d_in, const int* in_sizes, int n_in,
                              void* d_out, int out_size) {
    const float* x    = (const float*)d_in[0];
    const float* beta = (const float*)d_in[1];
    const float* Wq   = (const float*)d_in[2];
    const float* bq   = (const float*)d_in[3];
    const float* Wk   = (const float*)d_in[4];
    const float* bk   = (const float*)d_in[5];
    const float* Wv   = (const float*)d_in[6];
    const float* bv   = (const float*)d_in[7];
    const float* Wo   = (const float*)d_in[8];
    const float* bo   = (const float*)d_in[9];
    float* out = (float*)d_out;

    cudaFuncSetAttribute(qkv_kernel, cudaFuncAttributeMaxDynamicSharedMemorySize,
                         GEMM_SMEM_BYTES);
    cudaFuncSetAttribute(oproj_kernel, cudaFuncAttributeMaxDynamicSharedMemorySize,
                         GEMM_SMEM_BYTES);
    cudaFuncSetAttribute(attn_kernel, cudaFuncAttributeMaxDynamicSharedMemorySize,
                         ATTN_SMEM_BYTES);

    // pack x (A-frags, mode 0) and all weights (B-frags), tf32-rounded
    pack_a_kernel<<<(SEQL * DMODEL / 4) / 256, 256>>>(x, 0);
    pack_b_kernel<<<dim3((DMODEL * DMODEL / 2) / 256, 4), 256>>>(Wq, Wk, Wv, Wo);

    qkv_kernel<<<dim3(DMODEL / 128, SEQL / 128, 3), TPB, GEMM_SMEM_BYTES>>>(
        bq, bk, bv, beta);
    attn_kernel<<<dim3(SPRIME / QTILE, 4, NHEAD), TPB, ATTN_SMEM_BYTES>>>();
    pack_a_kernel<<<(SEQL * DMODEL / 4) / 256, 256>>>(nullptr, 1);  // g_ctx -> g_packC
    oproj_kernel<<<dim3(DMODEL / 128, SEQL / 128), TPB, GEMM_SMEM_BYTES>>>(bo, out);
}

// round 15
// speedup vs baseline: 1.0107x; 1.0107x over previous
#include <cuda_runtime.h>
#include <math.h>
#include <stdint.h>

#define TPB 256
#define SEQL 3072
#define DMODEL 1024
#define NHEAD 16
#define DHEAD 64
#define SPRIME 768      // SEQL / 4 (dilation)
#define KTILE 192       // 127 + 64 key rows per attention tile
#define QTILE 64
#define KBLKS (DMODEL / 8)   // 128

// ---------------- scratch (device globals; no allocation allowed) -------------
__device__ __align__(16) float g_q[NHEAD * 4 * SPRIME * DHEAD];
__device__ __align__(16) float g_k[NHEAD * 4 * SPRIME * DHEAD];
__device__ __align__(16) float g_v[NHEAD * 4 * SPRIME * DHEAD];
__device__ __align__(16) float g_ctx[SEQL * DMODEL];
// fragment-packed operands (tf32-rounded):
__device__ __align__(16) float g_packX[SEQL * DMODEL];       // A-frag pack of x
__device__ __align__(16) float g_packC[SEQL * DMODEL];       // A-frag pack of ctx
__device__ __align__(16) float g_packW[4 * DMODEL * DMODEL]; // B-frag packs Wq,Wk,Wv,Wo

// ---------------- tf32 helpers -----------------------------------------------
__device__ __forceinline__ unsigned f2tf(float f) {
    unsigned u;
    asm("cvt.rna.tf32.f32 %0, %1;" : "=r"(u) : "f"(f));
    return u;
}

__device__ __forceinline__ void mma8(float* c, const unsigned* a, const unsigned* b) {
    asm volatile(
        "mma.sync.aligned.m16n8k8.row.col.f32.tf32.tf32.f32 "
        "{%0,%1,%2,%3}, {%4,%5,%6,%7}, {%8,%9}, {%0,%1,%2,%3};"
        : "+f"(c[0]), "+f"(c[1]), "+f"(c[2]), "+f"(c[3])
        : "r"(a[0]), "r"(a[1]), "r"(a[2]), "r"(a[3]),
          "r"(b[0]), "r"(b[1]));
}

// ---------------- cp.async helpers --------------------------------------------
__device__ __forceinline__ void cpasync16(void* s, const void* g) {
    unsigned saddr = (unsigned)__cvta_generic_to_shared(s);
    asm volatile("cp.async.cg.shared.global [%0], [%1], 16;\n" :: "r"(saddr), "l"(g));
}
__device__ __forceinline__ void cpcommit() {
    asm volatile("cp.async.commit_group;\n");
}
template<int N> __device__ __forceinline__ void cpwait() {
    asm volatile("cp.async.wait_group %0;\n" :: "n"(N));
}

// ---------------- pack kernels -------------------------------------------------
// Fused input pack: blockIdx.y == 0 -> A-frag pack of x into g_packX;
// blockIdx.y == 1..4 -> B-frag pack of Wq/Wk/Wv/Wo into g_packW.
__global__ void __launch_bounds__(256) pack_in_kernel(
    const float* __restrict__ x,
    const float* __restrict__ Wq, const float* __restrict__ Wk,
    const float* __restrict__ Wv, const float* __restrict__ Wo) {
    const int y = blockIdx.y;
    if (y == 0) {
        const unsigned u = blockIdx.x * 256 + threadIdx.x;   // one float4 out
        const unsigned l = u & 31, blk = u >> 5;
        const unsigned KB = blk & (KBLKS - 1), MB = blk >> 7;
        const unsigned gid = l >> 2, tig = l & 3;
        const float* p = x + (size_t)(MB * 16 + gid) * DMODEL + KB * 8 + tig;
        uint4 o;
        o.x = f2tf(p[0]);
        o.y = f2tf(p[8 * DMODEL]);
        o.z = f2tf(p[4]);
        o.w = f2tf(p[8 * DMODEL + 4]);
        *((uint4*)g_packX + u) = o;
    } else {
        if (blockIdx.x >= (DMODEL * DMODEL / 2) / 256) return;
        const int z = y - 1;
        const float* W = (z == 0) ? Wq : ((z == 1) ? Wk : ((z == 2) ? Wv : Wo));
        float* dst = g_packW + (size_t)z * DMODEL * DMODEL;
        const unsigned u = blockIdx.x * 256 + threadIdx.x;   // one float2 out
        const unsigned l = u & 31, blk = u >> 5;
        const unsigned KB = blk & (KBLKS - 1), NB = blk >> 7;
        const unsigned gid = l >> 2, tig = l & 3;
        const float* p = W + (size_t)(NB * 8 + gid) * DMODEL + KB * 8 + tig;
        uint2 o;
        o.x = f2tf(p[0]);
        o.y = f2tf(p[4]);
        *((uint2*)dst + u) = o;
    }
}

// A-frag pack of g_ctx into g_packC (between attn and oproj)
__global__ void __launch_bounds__(256) pack_ctx_kernel() {
    const unsigned u = blockIdx.x * 256 + threadIdx.x;   // one float4 out
    const unsigned l = u & 31, blk = u >> 5;
    const unsigned KB = blk & (KBLKS - 1), MB = blk >> 7;
    const unsigned gid = l >> 2, tig = l & 3;
    const float* p = g_ctx + (size_t)(MB * 16 + gid) * DMODEL + KB * 8 + tig;
    uint4 o;
    o.x = f2tf(p[0]);
    o.y = f2tf(p[8 * DMODEL]);
    o.z = f2tf(p[4]);
    o.w = f2tf(p[8 * DMODEL + 4]);
    *((uint4*)g_packC + u) = o;
}

// ---------------- packed-fragment GEMM: C[128x128] -----------------------------
#define GBK 32
#define GNCH (DMODEL / GBK)                  // 32
#define CHUNK_F 4096                         // floats per operand chunk (16KB)
#define GEMM_SMEM_BYTES (4 * CHUNK_F * 4)    // 65536

__device__ __forceinline__ void gemm_body(const float* __restrict__ Ap,
                                          const float* __restrict__ Bp,
                                          int mb0, int nb0,
                                          float (&c)[2][8][4], float* sm) {
    float* sA[2] = { sm, sm + CHUNK_F };
    float* sB[2] = { sm + 2 * CHUNK_F, sm + 3 * CHUNK_F };

    const int tid  = threadIdx.x;
    const int lane = tid & 31, warp = tid >> 5;
    const int wm2 = (warp & 3) * 2;     // chunk-local mblk base
    const int wn8 = (warp >> 2) * 8;    // chunk-local nblk base

    auto stage = [&](int ch, int b) {
        const int kb0 = ch * 4;
        #pragma unroll
        for (int t = 0; t < 4; t++) {
            unsigned u = tid + t * 256;            // A 16B-unit
            unsigned i = u >> 7, j = (u >> 5) & 3, l = u & 31;
            const float* srcA = Ap + ((size_t)((mb0 + i) * KBLKS + kb0 + j) * 32 + l) * 4;
            cpasync16(sA[b] + u * 4, srcA);
        }
        #pragma unroll
        for (int t = 0; t < 4; t++) {
            unsigned u = tid + t * 256;            // B 16B-unit (2 lanes x float2)
            unsigned inb = u >> 6, rem = u & 63;
            unsigned j = rem >> 4, lp = (rem & 15) * 2;
            const float* srcB = Bp + ((size_t)((nb0 + inb) * KBLKS + kb0 + j) * 32 + lp) * 2;
            cpasync16(sB[b] + u * 4, srcB);
        }
        cpcommit();
    };

    stage(0, 0);

    for (int ch = 0; ch < GNCH; ch++) {
        const int b = ch & 1;
        if (ch + 1 < GNCH) { stage(ch + 1, b ^ 1); cpwait<1>(); }
        else               { cpwait<0>(); }
        __syncthreads();

        const float* a_s = sA[b];
        const float* b_s = sB[b];
        #pragma unroll
        for (int ks8 = 0; ks8 < 4; ks8++) {
            uint4 a[2];
            uint2 bb[8];
            #pragma unroll
            for (int mt = 0; mt < 2; mt++)
                a[mt] = *(const uint4*)(a_s + (((wm2 + mt) * 4 + ks8) * 32 + lane) * 4);
            #pragma unroll
            for (int nt = 0; nt < 8; nt++)
                bb[nt] = *(const uint2*)(b_s + (((wn8 + nt) * 4 + ks8) * 32 + lane) * 2);
            #pragma unroll
            for (int mt = 0; mt < 2; mt++)
                #pragma unroll
                for (int nt = 0; nt < 8; nt++)
                    mma8(c[mt][nt], (const unsigned*)&a[mt], (const unsigned*)&bb[nt]);
        }
        __syncthreads();
    }
}

// ---------------- QKV projection -----------------------------------------------
__global__ void __launch_bounds__(TPB, 2) qkv_kernel(
    const float* __restrict__ bq, const float* __restrict__ bk,
    const float* __restrict__ bv, const float* __restrict__ beta)
{
    extern __shared__ float sm[];
    const int z = blockIdx.z;
    const float* Bp   = g_packW + (size_t)z * DMODEL * DMODEL;
    const float* bias = (z == 0) ? bq : ((z == 1) ? bk : bv);
    float* outp       = (z == 0) ? g_q : ((z == 1) ? g_k : g_v);
    const int m0 = blockIdx.y * 128, n0 = blockIdx.x * 128;

    float c[2][8][4];
    #pragma unroll
    for (int mt = 0; mt < 2; mt++)
        #pragma unroll
        for (int nt = 0; nt < 8; nt++)
            #pragma unroll
            for (int k = 0; k < 4; k++) c[mt][nt][k] = 0.f;

    gemm_body(g_packX, Bp, m0 / 16, n0 / 8, c, sm);

    const int lane = threadIdx.x & 31, warp = threadIdx.x >> 5;
    const int wm = (warp & 3) * 32, wn = (warp >> 2) * 64;
    const int gid = lane >> 2, tig = lane & 3;

    #pragma unroll
    for (int mt = 0; mt < 2; mt++) {
        #pragma unroll
        for (int nt = 0; nt < 8; nt++) {
            int n_c = n0 + wn + nt * 8 + tig * 2;
            int h = n_c >> 6, d0 = n_c & 63;
            float sc = 1.0f;
            if (z == 0) sc = 0.125f * __expf(-beta[h]);   // fold 1/(8*exp(beta)) into Q
            float b0 = bias[n_c], b1 = bias[n_c + 1];
            #pragma unroll
            for (int half = 0; half < 2; half++) {
                int s  = m0 + wm + mt * 16 + gid + half * 8;
                int rr = s & 3, sp = s >> 2;
                float v0 = (c[mt][nt][half * 2 + 0] + b0) * sc;
                float v1 = (c[mt][nt][half * 2 + 1] + b1) * sc;
                float2* dst = (float2*)(outp + (((h * 4 + rr) * SPRIME + sp) * DHEAD + d0));
                *dst = make_float2(v0, v1);
            }
        }
    }
}

// ---------------- output projection --------------------------------------------
__global__ void __launch_bounds__(TPB, 2) oproj_kernel(
    const float* __restrict__ bo, float* __restrict__ out)
{
    extern __shared__ float sm[];
    const int m0 = blockIdx.y * 128, n0 = blockIdx.x * 128;

    float c[2][8][4];
    #pragma unroll
    for (int mt = 0; mt < 2; mt++)
        #pragma unroll
        for (int nt = 0; nt < 8; nt++)
            #pragma unroll
            for (int k = 0; k < 4; k++) c[mt][nt][k] = 0.f;

    gemm_body(g_packC, g_packW + (size_t)3 * DMODEL * DMODEL, m0 / 16, n0 / 8, c, sm);

    const int lane = threadIdx.x & 31, warp = threadIdx.x >> 5;
    const int wm = (warp & 3) * 32, wn = (warp >> 2) * 64;
    const int gid = lane >> 2, tig = lane & 3;

    #pragma unroll
    for (int mt = 0; mt < 2; mt++) {
        #pragma unroll
        for (int nt = 0; nt < 8; nt++) {
            int n_c = n0 + wn + nt * 8 + tig * 2;
            float b0 = bo[n_c], b1 = bo[n_c + 1];
            #pragma unroll
            for (int half = 0; half < 2; half++) {
                int mrow = m0 + wm + mt * 16 + gid + half * 8;
                float2* dst = (float2*)(out + (size_t)mrow * DMODEL + n_c);
                *dst = make_float2(c[mt][nt][half * 2 + 0] + b0,
                                   c[mt][nt][half * 2 + 1] + b1);
            }
        }
    }
}

// ---------------- attention over dilated windows (R13 phase-1 + fast exp) ------
// smem: sK [192][SQR=68] | sVt [64][SVR=197]; sS [64][SSR=196] ALIASES sK.
// Phase ordering + barriers make the alias safe.
// Q preloaded per-thread from global as mma fragments (register-resident).
#define SQR 68
#define SVR 197
#define SSR 196
#define ATTN_SMEM_FLOATS (KTILE * SQR + 64 * SVR)       // 13056 + 12608 = 25664
#define ATTN_SMEM_BYTES (ATTN_SMEM_FLOATS * 4)          // 102656 -> 2 CTAs/SM

__global__ void __launch_bounds__(TPB, 2) attn_kernel() {
    extern __shared__ float smA[];
    float* sK  = smA;                      // [192][SQR]
    float* sVt = smA + KTILE * SQR;        // [64][SVR]
    float* sS  = smA;                      // [64][SSR] alias of sK block

    const int tid = threadIdx.x;
    const int lane = tid & 31, warp = tid >> 5;
    const int gid = lane >> 2, tig = lane & 3;
    const int qt = blockIdx.x, r = blockIdx.y, h = blockIdx.z;
    const int q0 = qt * QTILE;
    const int kbase = q0 - 127;
    const float* Qb = g_q + (h * 4 + r) * SPRIME * DHEAD;
    const float* Kb = g_k + (h * 4 + r) * SPRIME * DHEAD;
    const float* Vb = g_v + (h * 4 + r) * SPRIME * DHEAD;

    const int wm4 = (warp & 3) * 16;
    const int wn2 = (warp >> 2) * 96;
    const int rq  = wm4 + gid;

    // ---- preload Q fragments from global (issues early, overlaps staging) ----
    float qv[8][4];
    #pragma unroll
    for (int ks8 = 0; ks8 < 8; ks8++) {
        const float* qp = Qb + (q0 + rq) * DHEAD + ks8 * 8 + tig;
        qv[ks8][0] = qp[0];
        qv[ks8][1] = qp[8 * DHEAD];
        qv[ks8][2] = qp[4];
        qv[ks8][3] = qp[8 * DHEAD + 4];
    }

    // ---- stage K row-major + V transposed (zero-fill out-of-range j) ----
    #pragma unroll
    for (int i = 0; i < 12; i++) {
        int lin = tid + i * TPB;
        int rk = lin >> 4, dg = (lin & 15) * 4;
        int j = kbase + rk;
        float4 kv = make_float4(0.f, 0.f, 0.f, 0.f);
        float4 vv = make_float4(0.f, 0.f, 0.f, 0.f);
        if (j >= 0 && j < SPRIME) {
            kv = *(const float4*)(Kb + j * DHEAD + dg);
            vv = *(const float4*)(Vb + j * DHEAD + dg);
        }
        *(float4*)(sK + rk * SQR + dg) = kv;
        sVt[(dg + 0) * SVR + rk] = vv.x;
        sVt[(dg + 1) * SVR + rk] = vv.y;
        sVt[(dg + 2) * SVR + rk] = vv.z;
        sVt[(dg + 3) * SVR + rk] = vv.w;
    }
    __syncthreads();

    // ---- phase 1: S = Q.K^T via 3xTF32 (accumulators stay in regs) ----
    float c[12][4];
    #pragma unroll
    for (int nt = 0; nt < 12; nt++)
        #pragma unroll
        for (int k = 0; k < 4; k++) c[nt][k] = 0.f;

    #pragma unroll
    for (int ks8 = 0; ks8 < 8; ks8++) {
        const int ks = ks8 * 8;
        unsigned ah[4], al[4];
        #pragma unroll
        for (int j = 0; j < 4; j++) {
            ah[j] = f2tf(qv[ks8][j]);
            al[j] = f2tf(qv[ks8][j] - __uint_as_float(ah[j]));
        }
        #pragma unroll
        for (int nt = 0; nt < 12; nt++) {
            int cb = wn2 + nt * 8 + gid;
            float y0 = sK[cb * SQR + ks + tig];
            float y1 = sK[cb * SQR + ks + tig + 4];
            unsigned bh[2], bl[2];
            bh[0] = f2tf(y0); bl[0] = f2tf(y0 - __uint_as_float(bh[0]));
            bh[1] = f2tf(y1); bl[1] = f2tf(y1 - __uint_as_float(bh[1]));
            mma8(c[nt], ah, bh);
            mma8(c[nt], ah, bl);
            mma8(c[nt], al, bh);
        }
    }
    __syncthreads();     // all K reads complete before S overwrites the block

    #pragma unroll
    for (int nt = 0; nt < 12; nt++) {
        int col = wn2 + nt * 8 + tig * 2;
        *(float2*)(sS + (wm4 + gid) * SSR + col) = make_float2(c[nt][0], c[nt][1]);
        *(float2*)(sS + (wm4 + gid + 8) * SSR + col) = make_float2(c[nt][2], c[nt][3]);
    }
    __syncthreads();

    // ---- phase 2: softmax per query over its band (fast exp) ----
    {
        const int q = tid >> 2, sub = tid & 3;
        int lo = q;
        int lim = 127 - q0;
        if (lim > lo) lo = lim;
        const int hi = q + 127;
        float* row = sS + q * SSR;

        float mx = -3.0e38f;
        for (int rk = lo + sub; rk <= hi; rk += 4)
            mx = fmaxf(mx, row[rk]);
        mx = fmaxf(mx, __shfl_xor_sync(0xffffffffu, mx, 1));
        mx = fmaxf(mx, __shfl_xor_sync(0xffffffffu, mx, 2));

        float sum = 0.f;
        for (int rk = lo + sub; rk <= hi; rk += 4)
            sum += __expf(row[rk] - mx);
        sum += __shfl_xor_sync(0xffffffffu, sum, 1);
        sum += __shfl_xor_sync(0xffffffffu, sum, 2);
        const float inv = 1.0f / sum;

        for (int rk = sub; rk < KTILE; rk += 4) {
            float p = 0.f;
            if (rk >= lo && rk <= hi)
                p = __expf(row[rk] - mx) * inv;
            row[rk] = p;
        }
    }
    __syncthreads();

    // ---- phase 3: ctx = P.V via tf32 mma ----
    {
        const int wn3 = (warp >> 2) * 32;
        float cc[4][4];
        #pragma unroll
        for (int nt = 0; nt < 4; nt++)
            #pragma unroll
            for (int k = 0; k < 4; k++) cc[nt][k] = 0.f;

        #pragma unroll 4
        for (int ks = 0; ks < KTILE; ks += 8) {
            unsigned a[4], b[4][2];
            a[0] = f2tf(sS[rq * SSR + ks + tig]);
            a[1] = f2tf(sS[(rq + 8) * SSR + ks + tig]);
            a[2] = f2tf(sS[rq * SSR + ks + tig + 4]);
            a[3] = f2tf(sS[(rq + 8) * SSR + ks + tig + 4]);
            #pragma unroll
            for (int nt = 0; nt < 4; nt++) {
                int dn = wn3 + nt * 8 + gid;
                b[nt][0] = f2tf(sVt[dn * SVR + ks + tig]);
                b[nt][1] = f2tf(sVt[dn * SVR + ks + tig + 4]);
            }
            #pragma unroll
            for (int nt = 0; nt < 4; nt++)
                mma8(cc[nt], a, b[nt]);
        }
        #pragma unroll
        for (int nt = 0; nt < 4; nt++) {
            int dn = wn3 + nt * 8 + tig * 2;
            #pragma unroll
            for (int half = 0; half < 2; half++) {
                int ql = wm4 + gid + half * 8;
                int s = (q0 + ql) * 4 + r;
                *(float2*)(g_ctx + (size_t)s * DMODEL + h * DHEAD + dn) =
                    make_float2(cc[nt][half * 2 + 0], cc[nt][half * 2 + 1]);
            }
        }
    }
}

// ---------------- launch --------------------------------------------------------
extern "C" void kernel_launch(void* const* d_in, const int* in_sizes, int n_in,
                              void* d_out, int out_size) {
    const float* x    = (const float*)d_in[0];
    const float* beta = (const float*)d_in[1];
    const float* Wq   = (const float*)d_in[2];
    const float* bq   = (const float*)d_in[3];
    const float* Wk   = (const float*)d_in[4];
    const float* bk   = (const float*)d_in[5];
    const float* Wv   = (const float*)d_in[6];
    const float* bv   = (const float*)d_in[7];
    const float* Wo   = (const float*)d_in[8];
    const float* bo   = (const float*)d_in[9];
    float* out = (float*)d_out;

    cudaFuncSetAttribute(qkv_kernel, cudaFuncAttributeMaxDynamicSharedMemorySize,
                         GEMM_SMEM_BYTES);
    cudaFuncSetAttribute(oproj_kernel, cudaFuncAttributeMaxDynamicSharedMemorySize,
                         GEMM_SMEM_BYTES);
    cudaFuncSetAttribute(attn_kernel, cudaFuncAttributeMaxDynamicSharedMemorySize,
                         ATTN_SMEM_BYTES);

    // fused pack of x (A-frags) + all weights (B-frags), tf32-rounded
    pack_in_kernel<<<dim3((SEQL * DMODEL / 4) / 256, 5), 256>>>(x, Wq, Wk, Wv, Wo);

    qkv_kernel<<<dim3(DMODEL / 128, SEQL / 128, 3), TPB, GEMM_SMEM_BYTES>>>(
        bq, bk, bv, beta);
    attn_kernel<<<dim3(SPRIME / QTILE, 4, NHEAD), TPB, ATTN_SMEM_BYTES>>>();
    pack_ctx_kernel<<<(SEQL * DMODEL / 4) / 256, 256>>>();
    oproj_kernel<<<dim3(DMODEL / 128, SEQL / 128), TPB, GEMM_SMEM_BYTES>>>(bo, out);
}